// round 11
// baseline (speedup 1.0000x reference)
#include <cuda_runtime.h>
#include <cstdint>

// Self-resetting work-stealing counters (graph-replay safe: last warp out
// resets both; every replay starts from zero).
__device__ unsigned g_ticket = 0;
__device__ unsigned g_done   = 0;

// Warp-cooperative backward scan (rel_err 0.0 proven): for each needy lane L,
// broadcast its packed words; lane j tests cycle t = 32w+32-j via popc;
// ballot finds the largest unstable t in one step.
__device__ __forceinline__ float warp_resolve(
    const unsigned (&pk)[8], int tot, float sc, bool needy, int lane, float res)
{
    const unsigned FULL = 0xffffffffu;
    unsigned m = __ballot_sync(FULL, needy);
    while (m) {
        const int L = __ffs(m) - 1;  m &= m - 1;          // owner lane (uniform)
        int   C  = __shfl_sync(FULL, tot, L);             // ones through word w
        float s  = __shfl_sync(FULL, sc,  L);
        float r  = -1.0f;
        #pragma unroll
        for (int w = 7; w >= 0; w--) {
            unsigned word = __shfl_sync(FULL, pk[w], L);
            int      tc   = 32 * w + 32 - lane;                 // cycle tested by lane
            unsigned abv  = word & (0xFFFFFFFEu << (31 - lane));// bits strictly above
            int      cnt  = C - __popc(abv);
            float    pp   = __fdiv_rn((float)cnt, (float)tc);   // IEEE div = reference
            bool     unst = fabsf((pp * 2.0f - 1.0f) - s) > 0.05f;
            unsigned bal  = __ballot_sync(FULL, unst);
            if (bal) {                                          // uniform branch
                int j = __ffs(bal) - 1;                         // lowest lane = largest t
                r = 1.0f - (float)(32 * w + 32 - j) * (1.0f / 256.0f);
                break;
            }
            C -= __popc(word);
        }
        if (r >= 0.0f && lane == L) res = r;
    }
    return res;
}

// PER-WARP work stealing, NO block syncs: each warp independently grabs
// 64-stream tiles (int2/lane, 8x LDG.64 front-batched = 2KB in flight/warp).
// 8192 tiles over 4144 warps (~2 tiles/warp) absorbs the between-SM L2-die
// spread; sibling warps keep DRAM saturated across each warp's ticket gap.
__global__ void __launch_bounds__(128, 7) stability_warpsteal(
    const float* __restrict__ src,
    const int2*  __restrict__ bits2,
    float2*      __restrict__ out,
    int n2, int ntiles)
{
    const unsigned FULL = 0xffffffffu;
    const int lane = threadIdx.x & 31;

    for (;;) {
        unsigned tile;
        if (lane == 0) tile = atomicAdd(&g_ticket, 1u);
        tile = __shfl_sync(FULL, tile, 0);
        if (tile >= (unsigned)ntiles) break;

        const int i = (int)tile * 32 + lane;          // int2-stream index
        float2 s2 = __ldg((const float2*)src + i);    // overlaps mainloop
        const int2* p = bits2 + i;

        unsigned pk0[8], pk1[8];
        #pragma unroll
        for (int w = 0; w < 8; w++) { pk0[w] = 0u; pk1[w] = 0u; }

        #pragma unroll
        for (int w = 0; w < 8; w++) {
            #pragma unroll
            for (int k = 0; k < 32; k += 8) {
                const int t = w * 32 + k;
                // 8 LDG.64 front-batched (2KB in flight per warp)
                int2 a = __ldcs(p + (size_t)(t + 0) * n2);
                int2 b = __ldcs(p + (size_t)(t + 1) * n2);
                int2 c = __ldcs(p + (size_t)(t + 2) * n2);
                int2 d = __ldcs(p + (size_t)(t + 3) * n2);
                int2 e = __ldcs(p + (size_t)(t + 4) * n2);
                int2 f = __ldcs(p + (size_t)(t + 5) * n2);
                int2 g = __ldcs(p + (size_t)(t + 6) * n2);
                int2 h = __ldcs(p + (size_t)(t + 7) * n2);
                unsigned y0 = (unsigned)(a.x | (b.x << 1) | (c.x << 2) | (d.x << 3) |
                                         (e.x << 4) | (f.x << 5) | (g.x << 6) | (h.x << 7));
                unsigned y1 = (unsigned)(a.y | (b.y << 1) | (c.y << 2) | (d.y << 3) |
                                         (e.y << 4) | (f.y << 5) | (g.y << 6) | (h.y << 7));
                pk0[w] += y0 << k;
                pk1[w] += y1 << k;
            }
        }

        float sc0 = fminf(fmaxf(s2.x, -1.0f), 1.0f);
        float sc1 = fminf(fmaxf(s2.y, -1.0f), 1.0f);

        int t0 = 0, t1 = 0;
        #pragma unroll
        for (int w = 0; w < 8; w++) { t0 += __popc(pk0[w]); t1 += __popc(pk1[w]); }

        // t=256 check: pp*2-1 = tot/128-1 exactly; pe rounds once like reference.
        bool n0 = !(fabsf((float)t0 * (1.0f / 128.0f) - 1.0f - sc0) > 0.05f);
        bool n1 = !(fabsf((float)t1 * (1.0f / 128.0f) - 1.0f - sc1) > 0.05f);

        const float DEF = 1.0f - 1.0f / 256.0f;  // never-unstable: cts=0 -> clip 1
        float r0 = n0 ? DEF : 0.0f;
        float r1 = n1 ? DEF : 0.0f;

        r0 = warp_resolve(pk0, t0, sc0, n0, lane, r0);
        r1 = warp_resolve(pk1, t1, sc1, n1, lane, r1);

        __stcs(out + i, make_float2(r0, r1));
    }

    // Reset protocol: last warp out zeroes both counters for the next replay.
    if (lane == 0) {
        __threadfence();
        unsigned total_warps = gridDim.x * (blockDim.x >> 5);
        unsigned d = atomicAdd(&g_done, 1u);
        if (d == total_warps - 1) {
            g_ticket = 0u;
            g_done   = 0u;
            __threadfence();
        }
    }
}

extern "C" void kernel_launch(void* const* d_in, const int* in_sizes, int n_in,
                              void* d_out, int out_size)
{
    const float* src  = (const float*)d_in[0];
    const int*   bits = (const int*)d_in[1];
    float*       out  = (float*)d_out;
    int N  = in_sizes[0];
    int n2 = N / 2;
    int ntiles = N / 64;                 // 8192 for N=524288

    stability_warpsteal<<<1036, 128>>>(src, (const int2*)bits,
                                       (float2*)out, n2, ntiles);
}

// round 12
// speedup vs baseline: 1.0735x; 1.0735x over previous
#include <cuda_runtime.h>
#include <cstdint>

// Warp-cooperative backward scan for one stream slot (rel_err 0.0 proven):
// for each needy lane L, broadcast its packed words; lane j tests cycle
// t = 32w+32-j via popc; ballot finds the largest unstable t in one step.
__device__ __forceinline__ float warp_resolve(
    const unsigned (&pk)[8], int tot, float sc, bool needy, int lane, float res)
{
    const unsigned FULL = 0xffffffffu;
    unsigned m = __ballot_sync(FULL, needy);
    while (m) {
        const int L = __ffs(m) - 1;  m &= m - 1;          // owner lane (uniform)
        int   C  = __shfl_sync(FULL, tot, L);             // ones through word w
        float s  = __shfl_sync(FULL, sc,  L);
        float r  = -1.0f;
        #pragma unroll
        for (int w = 7; w >= 0; w--) {
            unsigned word = __shfl_sync(FULL, pk[w], L);
            int      tc   = 32 * w + 32 - lane;                 // cycle tested by lane
            unsigned abv  = word & (0xFFFFFFFEu << (31 - lane));// bits strictly above
            int      cnt  = C - __popc(abv);
            float    pp   = __fdiv_rn((float)cnt, (float)tc);   // IEEE div = reference
            bool     unst = fabsf((pp * 2.0f - 1.0f) - s) > 0.05f;
            unsigned bal  = __ballot_sync(FULL, unst);
            if (bal) {                                          // uniform branch
                int j = __ffs(bal) - 1;                         // lowest lane = largest t
                r = 1.0f - (float)(32 * w + 32 - j) * (1.0f / 256.0f);
                break;
            }
            C -= __popc(word);
        }
        if (r >= 0.0f && lane == L) res = r;
    }
    return res;
}

// FINAL (record holder, R4): single-pass, SINGLE-WAVE kernel.
// 4 streams/thread via int4 (LDG.128, 4 front-batched = 2KB in flight/warp),
// grid = 1024 blocks @ 7 blocks/SM -> 1036 slots >= 1024, one wave, zero
// tail. Bits packed into 32 regs/thread; totals via popc; needy (~4%)
// resolved by the warp-cooperative ballot scan with zero extra traffic.
// Measured: ncu 87.4us, DRAM 78.6%, best bench 82.5us, rel_err 0.0.
// Dynamic-scheduling variants (block-sync, warp-steal) all regressed;
// this static shape is the converged optimum at the HBM streaming ceiling.
__global__ void __launch_bounds__(128, 7) stability_kernel(
    const float* __restrict__ src,
    const int4*  __restrict__ bits4,
    float4*      __restrict__ out,
    int n4)
{
    const int i = blockIdx.x * blockDim.x + threadIdx.x;
    const int lane = threadIdx.x & 31;
    if (i >= n4) return;   // grid sized exactly for N=524288; full warps

    unsigned pk0[8], pk1[8], pk2[8], pk3[8];
    #pragma unroll
    for (int w = 0; w < 8; w++) { pk0[w] = 0u; pk1[w] = 0u; pk2[w] = 0u; pk3[w] = 0u; }

    const int4* p = bits4 + i;
    #pragma unroll
    for (int w = 0; w < 8; w++) {
        #pragma unroll
        for (int k = 0; k < 32; k += 4) {
            const int t = w * 32 + k;
            int4 a = __ldcs(p + (size_t)(t    ) * n4);   // 4 LDG.128 front-batched
            int4 b = __ldcs(p + (size_t)(t + 1) * n4);
            int4 c = __ldcs(p + (size_t)(t + 2) * n4);
            int4 d = __ldcs(p + (size_t)(t + 3) * n4);
            // nibble = a + 2b + 4c + 8d (bits are 0/1)
            unsigned q0 = (unsigned)((b.x << 1) + a.x) + ((unsigned)((d.x << 1) + c.x) << 2);
            unsigned q1 = (unsigned)((b.y << 1) + a.y) + ((unsigned)((d.y << 1) + c.y) << 2);
            unsigned q2 = (unsigned)((b.z << 1) + a.z) + ((unsigned)((d.z << 1) + c.z) << 2);
            unsigned q3 = (unsigned)((b.w << 1) + a.w) + ((unsigned)((d.w << 1) + c.w) << 2);
            pk0[w] += q0 << k;
            pk1[w] += q1 << k;
            pk2[w] += q2 << k;
            pk3[w] += q3 << k;
        }
    }

    float4 s4 = ((const float4*)src)[i];
    float sc0 = fminf(fmaxf(s4.x, -1.0f), 1.0f);
    float sc1 = fminf(fmaxf(s4.y, -1.0f), 1.0f);
    float sc2 = fminf(fmaxf(s4.z, -1.0f), 1.0f);
    float sc3 = fminf(fmaxf(s4.w, -1.0f), 1.0f);

    int t0 = 0, t1 = 0, t2 = 0, t3 = 0;
    #pragma unroll
    for (int w = 0; w < 8; w++) {
        t0 += __popc(pk0[w]); t1 += __popc(pk1[w]);
        t2 += __popc(pk2[w]); t3 += __popc(pk3[w]);
    }

    // t=256 check: pp*2-1 = tot/128-1 exactly; pe rounds once like reference.
    bool n0 = !(fabsf((float)t0 * (1.0f / 128.0f) - 1.0f - sc0) > 0.05f);
    bool n1 = !(fabsf((float)t1 * (1.0f / 128.0f) - 1.0f - sc1) > 0.05f);
    bool n2 = !(fabsf((float)t2 * (1.0f / 128.0f) - 1.0f - sc2) > 0.05f);
    bool n3 = !(fabsf((float)t3 * (1.0f / 128.0f) - 1.0f - sc3) > 0.05f);

    const float DEF = 1.0f - 1.0f / 256.0f;   // never-unstable: cts=0 -> clip to 1
    float r0 = n0 ? DEF : 0.0f;
    float r1 = n1 ? DEF : 0.0f;
    float r2 = n2 ? DEF : 0.0f;
    float r3 = n3 ? DEF : 0.0f;

    r0 = warp_resolve(pk0, t0, sc0, n0, lane, r0);
    r1 = warp_resolve(pk1, t1, sc1, n1, lane, r1);
    r2 = warp_resolve(pk2, t2, sc2, n2, lane, r2);
    r3 = warp_resolve(pk3, t3, sc3, n3, lane, r3);

    out[i] = make_float4(r0, r1, r2, r3);
}

extern "C" void kernel_launch(void* const* d_in, const int* in_sizes, int n_in,
                              void* d_out, int out_size)
{
    const float* src  = (const float*)d_in[0];
    const int*   bits = (const int*)d_in[1];
    float*       out  = (float*)d_out;
    int N  = in_sizes[0];
    int n4 = N / 4;

    stability_kernel<<<(n4 + 127) / 128, 128>>>(src, (const int4*)bits,
                                                (float4*)out, n4);
}